// round 15
// baseline (speedup 1.0000x reference)
#include <cuda_runtime.h>
#include <cuda_bf16.h>
#include <math_constants.h>

#define BB 64
#define NN 2048
#define MM 64
#define NSEG 64          // NN/32 segments of 32 columns

// Scratch: costT[b][m][n] (f32), rewritten every launch, then poisoned (+INF
// on dirty columns). Segment min/argmin tables built by cost_kernel.
__device__ float g_costT[BB * MM * NN];
__device__ float g_segmin[BB * MM * NSEG];
__device__ short g_segarg[BB * MM * NSEG];

// ---------------------------------------------------------------------------
// Kernel 1: cost[b][n][m] = -ps[b][n][gs[b][m]] + sum_d |pb[b][n][d]-gb[b][m][d]|
// Also emits per-(row m, 32-col segment) min + first-argmin of costT.
// ---------------------------------------------------------------------------
__global__ void __launch_bounds__(512) cost_kernel(
    const float* __restrict__ ps, const float* __restrict__ pb,
    const int* __restrict__ gs, const float* __restrict__ gb,
    float* __restrict__ cost_out)
{
    const int b  = blockIdx.y;
    const int n0 = blockIdx.x * 64;
    const int t  = threadIdx.x;

    __shared__ float s_ps[64 * 2];
    __shared__ float s_pb[64 * 4];
    __shared__ float s_gb[64 * 4];
    __shared__ int   s_gs[64];
    __shared__ float tile[64][65];

    if (t < 128) s_ps[t] = ps[(b * NN + n0) * 2 + t];
    if (t < 256) s_pb[t] = pb[(b * NN + n0) * 4 + t];
    else         s_gb[t - 256] = gb[b * MM * 4 + (t - 256)];
    if (t < 64)  s_gs[t] = gs[b * MM + t];
    __syncthreads();

    const int out_base = (b * NN + n0) * MM;
#pragma unroll
    for (int k = 0; k < 8; k++) {
        int idx = t + k * 512;
        int nl = idx >> 6;
        int m  = idx & 63;
        float pres = -s_ps[nl * 2 + s_gs[m]];
        float l1 = fabsf(s_pb[nl * 4 + 0] - s_gb[m * 4 + 0]);
        l1 = l1 + fabsf(s_pb[nl * 4 + 1] - s_gb[m * 4 + 1]);
        l1 = l1 + fabsf(s_pb[nl * 4 + 2] - s_gb[m * 4 + 2]);
        l1 = l1 + fabsf(s_pb[nl * 4 + 3] - s_gb[m * 4 + 3]);
        float cv = pres + l1;
        tile[nl][m] = cv;
        cost_out[out_base + idx] = cv;
    }
    __syncthreads();

    const int ct_base = b * (MM * NN) + n0;
#pragma unroll
    for (int k = 0; k < 8; k++) {
        int idx = t + k * 512;
        int m  = idx >> 6;
        int nl = idx & 63;
        g_costT[ct_base + m * NN + nl] = tile[nl][m];
    }

    // segment min + first-argmin: this block covers segments n0/32 and n0/32+1
    if (t < 128) {
        int m = t & 63;
        int h = t >> 6;              // 0 or 1: which 32-col half
        float best = CUDART_INF_F; int barg = 0;
#pragma unroll
        for (int nl = 0; nl < 32; nl++) {
            float v = tile[h * 32 + nl][m];
            if (v < best) { best = v; barg = h * 32 + nl; }
        }
        int seg = (n0 >> 5) + h;
        g_segmin[(b * MM + m) * NSEG + seg] = best;
        g_segarg[(b * MM + m) * NSEG + seg] = (short)(n0 + barg);
    }
}

// monotone order-preserving maps
__device__ __forceinline__ unsigned fmapf(float x) {
    unsigned u = __float_as_uint(x);
    return (u & 0x80000000u) ? ~u : (u | 0x80000000u);
}
__device__ __forceinline__ float funmapf(unsigned m) {
    unsigned u = (m & 0x80000000u) ? (m ^ 0x80000000u) : ~m;
    return __uint_as_float(u);
}
__device__ __forceinline__ unsigned long long dmap(double d) {
    unsigned long long u = (unsigned long long)__double_as_longlong(d);
    return (u >> 63) ? ~u : (u | 0x8000000000000000ULL);
}
__device__ __forceinline__ double dunmap(unsigned long long m) {
    unsigned long long u = (m & 0x8000000000000000ULL) ? (m ^ 0x8000000000000000ULL) : ~m;
    return __longlong_as_double((long long)u);
}

// ---------------------------------------------------------------------------
// Kernel 2: warp-synchronous exact replication of the reference loop.
// Clean columns (v==0): served by the incremental segment-min table (smem only).
// Dirty columns (ever-used, <=63): exact f64 from a compact register list.
// ---------------------------------------------------------------------------
__global__ void __launch_bounds__(32) hungarian_kernel(
    float* __restrict__ out_row, float* __restrict__ out_col)
{
    const int b = blockIdx.x;
    const int l = threadIdx.x;
    float* base = g_costT + (size_t)b * MM * NN;
    const unsigned FULL = 0xffffffffu;

    __shared__ double s_u[MM + 1];
    __shared__ int    s_p[NN];
    __shared__ float  s_dc[MM][64];       // saved original c for dirty cols
    __shared__ signed char s_centry[NN];
    __shared__ float  s_segmin[MM][NSEG];
    __shared__ short  s_segarg[MM][NSEG];
    __shared__ int    s_col4row[MM];

    // per-lane dirty entry slots: entry e -> lane e%32, slot e/32
    int    dcol0 = -1, dcol1 = -1;
    double dv0 = 0.0, dv1 = 0.0;
    int    drow0 = 0, drow1 = 0;
    int    used0 = 0, used1 = 0;
    int    nd = 0;

    for (int j = l; j < NN; j += 32) { s_p[j] = 0; s_centry[j] = -1; }
#pragma unroll
    for (int k = 0; k < 3; k++) { int r = l + k * 32; if (r <= MM) s_u[r] = 0.0; }
    {   // load segment tables (coalesced)
        const float* gm = g_segmin + (size_t)b * MM * NSEG;
        const short* ga = g_segarg + (size_t)b * MM * NSEG;
        float* sm = &s_segmin[0][0];
        short* sa = &s_segarg[0][0];
#pragma unroll 8
        for (int idx = l; idx < MM * NSEG; idx += 32) { sm[idx] = gm[idx]; sa[idx] = ga[idx]; }
    }
    __syncwarp();

    for (int i = 1; i <= MM; i++) {
        int i0 = i;
        double u_i0 = s_u[i];

        for (;;) {
            // ---- clean scan: 2 LDS + 2 REDUX via segment table ----
            float a  = s_segmin[i0 - 1][l];
            float b2 = s_segmin[i0 - 1][l + 32];
            float mv = fminf(a, b2);
            unsigned wmin = __reduce_min_sync(FULL, fmapf(mv));
            float wm = funmapf(wmin);
            unsigned segc = (fmapf(a) == wmin) ? (unsigned)l :
                            ((fmapf(b2) == wmin) ? (unsigned)(l + 32) : 0xffffffffu);
            unsigned sseg = __reduce_min_sync(FULL, segc);
            int jclean = (int)s_segarg[i0 - 1][sseg];

            // ---- dirty scan: exact f64, ((c - u) - v), index tie-break ----
            unsigned long long bk = ~0ULL;
            unsigned bcol = 0xffffffffu;
            if (l < nd && !used0) {
                double cur = ((double)s_dc[i0 - 1][l] - u_i0) - dv0;
                unsigned long long k2 = dmap(cur);
                if (k2 < bk || (k2 == bk && (unsigned)dcol0 < bcol)) { bk = k2; bcol = (unsigned)dcol0; }
            }
            if (l + 32 < nd && !used1) {
                double cur = ((double)s_dc[i0 - 1][l + 32] - u_i0) - dv1;
                unsigned long long k2 = dmap(cur);
                if (k2 < bk || (k2 == bk && (unsigned)dcol1 < bcol)) { bk = k2; bcol = (unsigned)dcol1; }
            }
            unsigned hi   = (unsigned)(bk >> 32);
            unsigned hmin = __reduce_min_sync(FULL, hi);
            unsigned lo   = (hi == hmin) ? (unsigned)bk : 0xffffffffu;
            unsigned lmin = __reduce_min_sync(FULL, lo);
            unsigned cnd  = (hi == hmin && (unsigned)bk == lmin) ? bcol : 0xffffffffu;
            unsigned dcolw = __reduce_min_sync(FULL, cnd);
            bool haveDirty = (dcolw != 0xffffffffu);
            unsigned long long dkey = ((unsigned long long)hmin << 32) | lmin;

            int pclean = s_p[jclean];
            int pdirty = haveDirty ? s_p[dcolw] : 0;

            // ---- exact selection ----
            double cleancur = (double)wm - u_i0;      // v = 0 exactly on clean
            unsigned long long ckey = dmap(cleancur);
            bool pickDirty = haveDirty &&
                (dkey < ckey || (dkey == ckey && dcolw < (unsigned)jclean));
            double delta = pickDirty ? dunmap(dkey) : cleancur;
            int    j1    = pickDirty ? (int)dcolw : jclean;
            int    pj1   = pickDirty ? pdirty : pclean;

            // ---- dual updates (reference order) ----
            if (l < nd && used0)      { dv0 -= delta; s_u[drow0] += delta; }
            if (l + 32 < nd && used1) { dv1 -= delta; s_u[drow1] += delta; }
            if (l == 0) s_u[i] += delta;              // virtual column 0 (p[0]=i)
            __syncwarp();

            if (pj1 == 0) {
                if (l == 0) s_p[j1] = i;
                used0 = 0; used1 = 0;
                __syncwarp();
                break;
            }

            // ---- mark j1 used; first time: poison column + update seg table ----
            int e1 = (int)s_centry[j1];
            if (e1 < 0) {
                e1 = nd;
                if ((e1 & 31) == l) {
                    if (e1 < 32) { dcol0 = j1; dv0 = 0.0; }
                    else         { dcol1 = j1; dv1 = 0.0; }
                }
                if (l == 0) s_centry[j1] = (signed char)e1;
                // save original values, poison (lane l owns rows l, l+32)
                float v0 = base[(size_t)l * NN + j1];
                float v1 = base[(size_t)(l + 32) * NN + j1];
                s_dc[l][e1]      = v0;
                s_dc[l + 32][e1] = v1;
                base[(size_t)l * NN + j1]        = CUDART_INF_F;
                base[(size_t)(l + 32) * NN + j1] = CUDART_INF_F;
                nd++;
                // recompute this segment's min/argmin for rows l and l+32
                int sg = j1 >> 5;
#pragma unroll
                for (int rh = 0; rh < 2; rh++) {
                    int rr = l + rh * 32;
                    const float4* sp = reinterpret_cast<const float4*>(
                        base + (size_t)rr * NN + (sg << 5));
                    float bst = CUDART_INF_F; int ba = 0;
#pragma unroll
                    for (int c2 = 0; c2 < 8; c2++) {
                        float4 v = sp[c2];
                        if (v.x < bst) { bst = v.x; ba = c2 * 4 + 0; }
                        if (v.y < bst) { bst = v.y; ba = c2 * 4 + 1; }
                        if (v.z < bst) { bst = v.z; ba = c2 * 4 + 2; }
                        if (v.w < bst) { bst = v.w; ba = c2 * 4 + 3; }
                    }
                    s_segmin[rr][sg] = bst;
                    s_segarg[rr][sg] = (short)((sg << 5) + ba);
                }
            }
            if ((e1 & 31) == l) {
                if (e1 < 32) { used0 = 1; drow0 = pj1; }
                else         { used1 = 1; drow1 = pj1; }
            }
            __syncwarp();

            i0 = pj1;
            u_i0 = s_u[i0];
        }
    }

    // col4row[row-1] = matched column (0-based)
    for (int j = l; j < NN; j += 32) {
        int pj = s_p[j];
        if (pj > 0) s_col4row[pj - 1] = j;
    }
    __syncwarp();

    // argsort by prediction index (all distinct)
    for (int r = l; r < MM; r += 32) {
        int pred = s_col4row[r];
        int rank = 0;
#pragma unroll
        for (int g = 0; g < MM; g++) rank += (s_col4row[g] < pred) ? 1 : 0;
        out_row[b * MM + rank] = (float)pred;
        out_col[b * MM + rank] = (float)r;
    }
}

extern "C" void kernel_launch(void* const* d_in, const int* in_sizes, int n_in,
                              void* d_out, int out_size)
{
    const float* ps = (const float*)d_in[0];
    const float* pb = (const float*)d_in[1];
    const int*   gs = (const int*)  d_in[2];
    const float* gb = (const float*)d_in[3];
    float* out = (float*)d_out;

    dim3 g1(NN / 64, BB);
    cost_kernel<<<g1, 512>>>(ps, pb, gs, gb, out);

    const long cost_elems = (long)BB * NN * MM;
    const long idx_elems  = (long)BB * MM;
    if (out_size >= cost_elems + 2 * idx_elems) {
        float* row_out = out + cost_elems;
        float* col_out = row_out + idx_elems;
        hungarian_kernel<<<BB, 32>>>(row_out, col_out);
    }
}

// round 16
// speedup vs baseline: 1.5598x; 1.5598x over previous
#include <cuda_runtime.h>
#include <cuda_bf16.h>
#include <math_constants.h>

#define BB 64
#define NN 2048
#define MM 64
#define NSEG 64          // NN/32 segments of 32 columns

// Scratch: costT[b][m][n] (f32), rewritten every launch, then poisoned (+INF
// on dirty columns). Segment min/argmin tables built by cost_kernel.
__device__ float g_costT[BB * MM * NN];
__device__ float g_segmin[BB * MM * NSEG];
__device__ short g_segarg[BB * MM * NSEG];

// ---------------------------------------------------------------------------
// Kernel 1: cost[b][n][m] = -ps[b][n][gs[b][m]] + sum_d |pb[b][n][d]-gb[b][m][d]|
// Also emits per-(row m, 32-col segment) min + first-argmin of costT.
// ---------------------------------------------------------------------------
__global__ void __launch_bounds__(512) cost_kernel(
    const float* __restrict__ ps, const float* __restrict__ pb,
    const int* __restrict__ gs, const float* __restrict__ gb,
    float* __restrict__ cost_out)
{
    const int b  = blockIdx.y;
    const int n0 = blockIdx.x * 64;
    const int t  = threadIdx.x;

    __shared__ float s_ps[64 * 2];
    __shared__ float s_pb[64 * 4];
    __shared__ float s_gb[64 * 4];
    __shared__ int   s_gs[64];
    __shared__ float tile[64][65];

    if (t < 128) s_ps[t] = ps[(b * NN + n0) * 2 + t];
    if (t < 256) s_pb[t] = pb[(b * NN + n0) * 4 + t];
    else         s_gb[t - 256] = gb[b * MM * 4 + (t - 256)];
    if (t < 64)  s_gs[t] = gs[b * MM + t];
    __syncthreads();

    const int out_base = (b * NN + n0) * MM;
#pragma unroll
    for (int k = 0; k < 8; k++) {
        int idx = t + k * 512;
        int nl = idx >> 6;
        int m  = idx & 63;
        float pres = -s_ps[nl * 2 + s_gs[m]];
        float l1 = fabsf(s_pb[nl * 4 + 0] - s_gb[m * 4 + 0]);
        l1 = l1 + fabsf(s_pb[nl * 4 + 1] - s_gb[m * 4 + 1]);
        l1 = l1 + fabsf(s_pb[nl * 4 + 2] - s_gb[m * 4 + 2]);
        l1 = l1 + fabsf(s_pb[nl * 4 + 3] - s_gb[m * 4 + 3]);
        float cv = pres + l1;
        tile[nl][m] = cv;
        cost_out[out_base + idx] = cv;
    }
    __syncthreads();

    const int ct_base = b * (MM * NN) + n0;
#pragma unroll
    for (int k = 0; k < 8; k++) {
        int idx = t + k * 512;
        int m  = idx >> 6;
        int nl = idx & 63;
        g_costT[ct_base + m * NN + nl] = tile[nl][m];
    }

    // segment min + first-argmin: this block covers segments n0/32 and n0/32+1
    if (t < 128) {
        int m = t & 63;
        int h = t >> 6;              // 0 or 1: which 32-col half
        float best = CUDART_INF_F; int barg = 0;
#pragma unroll
        for (int nl = 0; nl < 32; nl++) {
            float v = tile[h * 32 + nl][m];
            if (v < best) { best = v; barg = h * 32 + nl; }
        }
        int seg = (n0 >> 5) + h;
        g_segmin[(b * MM + m) * NSEG + seg] = best;
        g_segarg[(b * MM + m) * NSEG + seg] = (short)(n0 + barg);
    }
}

// monotone order-preserving maps
__device__ __forceinline__ unsigned fmapf(float x) {
    unsigned u = __float_as_uint(x);
    return (u & 0x80000000u) ? ~u : (u | 0x80000000u);
}
__device__ __forceinline__ float funmapf(unsigned m) {
    unsigned u = (m & 0x80000000u) ? (m ^ 0x80000000u) : ~m;
    return __uint_as_float(u);
}
__device__ __forceinline__ unsigned long long dmap(double d) {
    unsigned long long u = (unsigned long long)__double_as_longlong(d);
    return (u >> 63) ? ~u : (u | 0x8000000000000000ULL);
}
__device__ __forceinline__ double dunmap(unsigned long long m) {
    unsigned long long u = (m & 0x8000000000000000ULL) ? (m ^ 0x8000000000000000ULL) : ~m;
    return __longlong_as_double((long long)u);
}

// ---------------------------------------------------------------------------
// Kernel 2: warp-synchronous exact replication of the reference loop.
// Clean columns (v==0): served by the incremental segment-min table (smem only).
// Dirty columns (ever-used, <=63): exact f64 from a compact register list.
// ---------------------------------------------------------------------------
__global__ void __launch_bounds__(32) hungarian_kernel(
    float* __restrict__ out_row, float* __restrict__ out_col)
{
    const int b = blockIdx.x;
    const int l = threadIdx.x;
    float* base = g_costT + (size_t)b * MM * NN;
    const unsigned FULL = 0xffffffffu;

    __shared__ double s_u[MM + 1];
    __shared__ int    s_p[NN];
    __shared__ float  s_dc[MM][64];       // saved original c for dirty cols
    __shared__ signed char s_centry[NN];
    __shared__ float  s_segmin[MM][NSEG];
    __shared__ short  s_segarg[MM][NSEG];
    __shared__ int    s_col4row[MM];

    // per-lane dirty entry slots: entry e -> lane e%32, slot e/32
    int    dcol0 = -1, dcol1 = -1;
    double dv0 = 0.0, dv1 = 0.0;
    int    drow0 = 0, drow1 = 0;
    int    used0 = 0, used1 = 0;
    int    nd = 0;

    for (int j = l; j < NN; j += 32) { s_p[j] = 0; s_centry[j] = -1; }
#pragma unroll
    for (int k = 0; k < 3; k++) { int r = l + k * 32; if (r <= MM) s_u[r] = 0.0; }
    {   // load segment tables (coalesced)
        const float* gm = g_segmin + (size_t)b * MM * NSEG;
        const short* ga = g_segarg + (size_t)b * MM * NSEG;
        float* sm = &s_segmin[0][0];
        short* sa = &s_segarg[0][0];
#pragma unroll 8
        for (int idx = l; idx < MM * NSEG; idx += 32) { sm[idx] = gm[idx]; sa[idx] = ga[idx]; }
    }
    __syncwarp();

    for (int i = 1; i <= MM; i++) {
        int i0 = i;
        double u_i0 = s_u[i];

        for (;;) {
            // ---- clean scan: 2 LDS + 2 REDUX via segment table ----
            float a  = s_segmin[i0 - 1][l];
            float b2 = s_segmin[i0 - 1][l + 32];
            float mv = fminf(a, b2);
            unsigned wmin = __reduce_min_sync(FULL, fmapf(mv));
            float wm = funmapf(wmin);
            unsigned segc = (fmapf(a) == wmin) ? (unsigned)l :
                            ((fmapf(b2) == wmin) ? (unsigned)(l + 32) : 0xffffffffu);
            unsigned sseg = __reduce_min_sync(FULL, segc);
            int jclean = (int)s_segarg[i0 - 1][sseg];

            // ---- dirty scan: exact f64, ((c - u) - v), index tie-break ----
            unsigned long long bk = ~0ULL;
            unsigned bcol = 0xffffffffu;
            if (l < nd && !used0) {
                double cur = ((double)s_dc[i0 - 1][l] - u_i0) - dv0;
                unsigned long long k2 = dmap(cur);
                if (k2 < bk || (k2 == bk && (unsigned)dcol0 < bcol)) { bk = k2; bcol = (unsigned)dcol0; }
            }
            if (l + 32 < nd && !used1) {
                double cur = ((double)s_dc[i0 - 1][l + 32] - u_i0) - dv1;
                unsigned long long k2 = dmap(cur);
                if (k2 < bk || (k2 == bk && (unsigned)dcol1 < bcol)) { bk = k2; bcol = (unsigned)dcol1; }
            }
            unsigned hi   = (unsigned)(bk >> 32);
            unsigned hmin = __reduce_min_sync(FULL, hi);
            unsigned lo   = (hi == hmin) ? (unsigned)bk : 0xffffffffu;
            unsigned lmin = __reduce_min_sync(FULL, lo);
            unsigned cnd  = (hi == hmin && (unsigned)bk == lmin) ? bcol : 0xffffffffu;
            unsigned dcolw = __reduce_min_sync(FULL, cnd);
            bool haveDirty = (dcolw != 0xffffffffu);
            unsigned long long dkey = ((unsigned long long)hmin << 32) | lmin;

            int pclean = s_p[jclean];
            int pdirty = haveDirty ? s_p[dcolw] : 0;

            // ---- exact selection ----
            double cleancur = (double)wm - u_i0;      // v = 0 exactly on clean
            unsigned long long ckey = dmap(cleancur);
            bool pickDirty = haveDirty &&
                (dkey < ckey || (dkey == ckey && dcolw < (unsigned)jclean));
            double delta = pickDirty ? dunmap(dkey) : cleancur;
            int    j1    = pickDirty ? (int)dcolw : jclean;
            int    pj1   = pickDirty ? pdirty : pclean;

            // ---- dual updates (reference order) ----
            if (l < nd && used0)      { dv0 -= delta; s_u[drow0] += delta; }
            if (l + 32 < nd && used1) { dv1 -= delta; s_u[drow1] += delta; }
            if (l == 0) s_u[i] += delta;              // virtual column 0 (p[0]=i)
            __syncwarp();

            if (pj1 == 0) {
                if (l == 0) s_p[j1] = i;
                used0 = 0; used1 = 0;
                __syncwarp();
                break;
            }

            // ---- mark j1 used; first time: poison column + update seg table ----
            int e1 = (int)s_centry[j1];
            if (e1 < 0) {
                e1 = nd;
                if ((e1 & 31) == l) {
                    if (e1 < 32) { dcol0 = j1; dv0 = 0.0; }
                    else         { dcol1 = j1; dv1 = 0.0; }
                }
                if (l == 0) s_centry[j1] = (signed char)e1;
                // save original values, poison (lane l owns rows l, l+32)
                float v0 = base[(size_t)l * NN + j1];
                float v1 = base[(size_t)(l + 32) * NN + j1];
                s_dc[l][e1]      = v0;
                s_dc[l + 32][e1] = v1;
                base[(size_t)l * NN + j1]        = CUDART_INF_F;
                base[(size_t)(l + 32) * NN + j1] = CUDART_INF_F;
                nd++;
                // recompute this segment's min/argmin for rows l and l+32
                int sg = j1 >> 5;
#pragma unroll
                for (int rh = 0; rh < 2; rh++) {
                    int rr = l + rh * 32;
                    const float4* sp = reinterpret_cast<const float4*>(
                        base + (size_t)rr * NN + (sg << 5));
                    float bst = CUDART_INF_F; int ba = 0;
#pragma unroll
                    for (int c2 = 0; c2 < 8; c2++) {
                        float4 v = sp[c2];
                        if (v.x < bst) { bst = v.x; ba = c2 * 4 + 0; }
                        if (v.y < bst) { bst = v.y; ba = c2 * 4 + 1; }
                        if (v.z < bst) { bst = v.z; ba = c2 * 4 + 2; }
                        if (v.w < bst) { bst = v.w; ba = c2 * 4 + 3; }
                    }
                    s_segmin[rr][sg] = bst;
                    s_segarg[rr][sg] = (short)((sg << 5) + ba);
                }
            }
            if ((e1 & 31) == l) {
                if (e1 < 32) { used0 = 1; drow0 = pj1; }
                else         { used1 = 1; drow1 = pj1; }
            }
            __syncwarp();

            i0 = pj1;
            u_i0 = s_u[i0];
        }
    }

    // col4row[row-1] = matched column (0-based)
    for (int j = l; j < NN; j += 32) {
        int pj = s_p[j];
        if (pj > 0) s_col4row[pj - 1] = j;
    }
    __syncwarp();

    // argsort by prediction index (all distinct)
    for (int r = l; r < MM; r += 32) {
        int pred = s_col4row[r];
        int rank = 0;
#pragma unroll
        for (int g = 0; g < MM; g++) rank += (s_col4row[g] < pred) ? 1 : 0;
        out_row[b * MM + rank] = (float)pred;
        out_col[b * MM + rank] = (float)r;
    }
}

extern "C" void kernel_launch(void* const* d_in, const int* in_sizes, int n_in,
                              void* d_out, int out_size)
{
    const float* ps = (const float*)d_in[0];
    const float* pb = (const float*)d_in[1];
    const int*   gs = (const int*)  d_in[2];
    const float* gb = (const float*)d_in[3];
    float* out = (float*)d_out;

    dim3 g1(NN / 64, BB);
    cost_kernel<<<g1, 512>>>(ps, pb, gs, gb, out);

    const long cost_elems = (long)BB * NN * MM;
    const long idx_elems  = (long)BB * MM;
    if (out_size >= cost_elems + 2 * idx_elems) {
        float* row_out = out + cost_elems;
        float* col_out = row_out + idx_elems;
        hungarian_kernel<<<BB, 32>>>(row_out, col_out);
    }
}